// round 11
// baseline (speedup 1.0000x reference)
#include <cuda_runtime.h>
#include <math.h>
#include <stdint.h>

#define C 16
#define F 16
#define H 12
#define HH 12
#define BROWS 262144
#define THREADS 256
#define ROWS_PER_BLOCK 256
#define NBLOCKS (BROWS / ROWS_PER_BLOCK)   // 1024
#define INV_COUNT (1.0f / 4194304.0f)

// Dynamic smem layout (float units)
#define XSTRIDE 20                              // conflict-free for frag loads, 16B-aligned rows
#define XBUF_STRIDE (ROWS_PER_BLOCK * XSTRIDE)  // 5120
#define XB0   0                                 // 2 * 5120 = 10240
#define HSTRIDE 14                              // EVEN: float2 accesses stay 8B-aligned
#define HB0   (XB0 + 2 * XBUF_STRIDE)           // 10240; 8 warps * 16*14 = 1792
#define WE_S  (HB0 + 8 * 16 * HSTRIDE)          // 12032; [16][12] stride 17 = 3264
#define WD_S  (WE_S + 16 * 12 * 17)             // 15296; [16][16] stride 12 = 3072
#define BE_S  (WD_S + 16 * 16 * 12)             // 18368; [16][16]
#define BD_S  (BE_S + 256)                      // 18624; [16][16]
#define SP_S  (BD_S + 256)                      // 18880
#define SMEM_FLOATS (SP_S + 16)                 // 18896
#define SMEM_BYTES (SMEM_FLOATS * 4)            // 75584 B -> 3 CTAs/SM

__device__ float g_sumsq[C];
__device__ unsigned int g_done;

__device__ __forceinline__ float tanh_ap(float x) {
    float y; asm("tanh.approx.f32 %0, %1;" : "=f"(y) : "f"(x)); return y;
}
__device__ __forceinline__ float sigm(float z) {
    return fmaf(0.5f, tanh_ap(0.5f * z), 0.5f);
}
__device__ __forceinline__ uint32_t cvt_tf32(float x) {
    uint32_t u; asm("cvt.rna.tf32.f32 %0, %1;" : "=r"(u) : "f"(x)); return u;
}
__device__ __forceinline__ void mma_tf32(float& c0, float& c1, float& c2, float& c3,
                                         uint32_t a0, uint32_t a1, uint32_t a2, uint32_t a3,
                                         uint32_t b0, uint32_t b1) {
    asm("mma.sync.aligned.m16n8k8.row.col.f32.tf32.tf32.f32 "
        "{%0,%1,%2,%3}, {%4,%5,%6,%7}, {%8,%9}, {%0,%1,%2,%3};"
        : "+f"(c0), "+f"(c1), "+f"(c2), "+f"(c3)
        : "r"(a0), "r"(a1), "r"(a2), "r"(a3), "r"(b0), "r"(b1));
}
__device__ __forceinline__ uint32_t smem_u32(const void* p) {
    return (uint32_t)__cvta_generic_to_shared(p);
}
__device__ __forceinline__ void cp16(uint32_t dst, const void* src) {
    asm volatile("cp.async.ca.shared.global [%0], [%1], 16;" :: "r"(dst), "l"(src));
}

__global__ __launch_bounds__(THREADS, 3) void autoenc_mma_kernel(
    const float* __restrict__ x,
    const float* __restrict__ gWe,  // [C][H][F]
    const float* __restrict__ gbe,  // [C][H]
    const float* __restrict__ gWd,  // [C][F][H]
    const float* __restrict__ gbd,  // [C][F]
    const float* __restrict__ He,   // [HH][C]
    const float* __restrict__ hbe,  // [HH]
    const float* __restrict__ Hd,   // [C][HH]
    const float* __restrict__ hbd,  // [C]
    float* __restrict__ out)        // [0:16) head_out, [16:32) tails
{
    extern __shared__ __align__(16) float smf[];
    const int tid  = threadIdx.x;
    const int warp = tid >> 5;
    const int lane = tid & 31;
    const int g    = lane >> 2;   // groupID (row within m16)
    const int tig  = lane & 3;    // thread-in-group (col base)

    // ---- Stage weights (tf32-converted) and biases into smem ----
    for (int i = tid; i < C * H * F; i += THREADS) {
        int c = i / (H * F);
        int r = i - c * (H * F);
        int h = r / F;
        int f = r - h * F;
        smf[WE_S + (c * H + h) * 17 + f] = __uint_as_float(cvt_tf32(gWe[i]));
    }
    for (int i = tid; i < C * F * H; i += THREADS) {
        int c = i / (F * H);
        int r = i - c * (F * H);
        int f = r / H;
        int h = r - f * H;
        smf[WD_S + (c * F + f) * 12 + h] = __uint_as_float(cvt_tf32(gWd[i]));
    }
    for (int i = tid; i < 256; i += THREADS) {
        int c = i >> 4, h = i & 15;
        smf[BE_S + i] = (h < H) ? gbe[c * H + h] : 0.0f;  // f32 exact (C operand)
        smf[BD_S + i] = gbd[i];
    }
    if (tid < C) smf[SP_S + tid] = 0.0f;

    const int rowbase = blockIdx.x * ROWS_PER_BLOCK;

    // cp.async issue of one cluster's x tile into buffer `buf`
    auto issue_x = [&](int c, int buf) {
        #pragma unroll
        for (int j = 0; j < 4; ++j) {
            int idx = j * THREADS + tid;       // 1024 float4 chunks (256 rows x 4)
            int r = idx >> 2, k = idx & 3;
            uint32_t dst = smem_u32(smf + XB0 + buf * XBUF_STRIDE + r * XSTRIDE + k * 4);
            const float* src = x + (size_t)(rowbase + r) * (C * F) + c * F + k * 4;
            cp16(dst, src);
        }
        asm volatile("cp.async.commit_group;");
    };

    issue_x(0, 0);

    float* hb = smf + HB0 + warp * (16 * HSTRIDE);   // one 16x14 tile per warp

    #pragma unroll 1
    for (int c = 0; c < C; ++c) {
        asm volatile("cp.async.wait_group 0;");
        __syncthreads();          // buffer c ready AND previous buffer's readers done
        if (c < C - 1) issue_x(c + 1, (c + 1) & 1);

        const float* xb_base = smf + XB0 + (c & 1) * XBUF_STRIDE;

        // ---- Encoder B fragments: We[h][f], B[k=f][n=h]; h>=12 -> 0 ----
        uint32_t web[2][2][2];   // [ntile][kgroup][b0/b1]
        #pragma unroll
        for (int nt = 0; nt < 2; ++nt) {
            int h = g + 8 * nt;
            bool hv = (h < H);
            const float* wr = smf + WE_S + (c * H + (hv ? h : 0)) * 17;
            #pragma unroll
            for (int kg = 0; kg < 2; ++kg) {
                web[nt][kg][0] = hv ? __float_as_uint(wr[tig + 8 * kg])     : 0u;
                web[nt][kg][1] = hv ? __float_as_uint(wr[tig + 4 + 8 * kg]) : 0u;
            }
        }
        // ---- Decoder B fragments: Wd[f][h], B[k=h][n=f]; h>=12 -> 0 ----
        uint32_t wdb[2][2][2];
        #pragma unroll
        for (int nt = 0; nt < 2; ++nt) {
            int f = g + 8 * nt;
            const float* wr = smf + WD_S + (c * F + f) * 12;
            wdb[nt][0][0] = __float_as_uint(wr[tig]);
            wdb[nt][0][1] = __float_as_uint(wr[tig + 4]);
            wdb[nt][1][0] = __float_as_uint(wr[tig + 8]);
            wdb[nt][1][1] = 0u;
        }
        float2 bev[2], bdv[2];
        #pragma unroll
        for (int nt = 0; nt < 2; ++nt) {
            bev[nt] = *(const float2*)(smf + BE_S + c * 16 + 8 * nt + 2 * tig);
            bdv[nt] = *(const float2*)(smf + BD_S + c * 16 + 8 * nt + 2 * tig);
        }

        float e = 0.0f;

        #pragma unroll
        for (int s = 0; s < 2; ++s) {
            const float* xb = xb_base + (warp * 32 + s * 16) * XSTRIDE;

            // ---- x A-fragments (k = f), tf32-converted ----
            uint32_t xa[2][4];
            #pragma unroll
            for (int kg = 0; kg < 2; ++kg) {
                xa[kg][0] = cvt_tf32(xb[g * XSTRIDE + tig + 8 * kg]);
                xa[kg][1] = cvt_tf32(xb[(g + 8) * XSTRIDE + tig + 8 * kg]);
                xa[kg][2] = cvt_tf32(xb[g * XSTRIDE + tig + 4 + 8 * kg]);
                xa[kg][3] = cvt_tf32(xb[(g + 8) * XSTRIDE + tig + 4 + 8 * kg]);
            }

            // ---- Encoder MMAs: Z[16 x 16(pad)] ----
            float zc[2][4];
            #pragma unroll
            for (int nt = 0; nt < 2; ++nt) {
                zc[nt][0] = bev[nt].x; zc[nt][1] = bev[nt].y;
                zc[nt][2] = bev[nt].x; zc[nt][3] = bev[nt].y;
                #pragma unroll
                for (int kg = 0; kg < 2; ++kg)
                    mma_tf32(zc[nt][0], zc[nt][1], zc[nt][2], zc[nt][3],
                             xa[kg][0], xa[kg][1], xa[kg][2], xa[kg][3],
                             web[nt][kg][0], web[nt][kg][1]);
            }

            // ---- sigmoid + store h tile (warp-private) ----
            __syncwarp();   // previous subtile's ha loads complete before overwrite
            {
                int col = 2 * tig;
                float2 lo = make_float2(__uint_as_float(cvt_tf32(sigm(zc[0][0]))),
                                        __uint_as_float(cvt_tf32(sigm(zc[0][1]))));
                float2 hi = make_float2(__uint_as_float(cvt_tf32(sigm(zc[0][2]))),
                                        __uint_as_float(cvt_tf32(sigm(zc[0][3]))));
                *(float2*)(hb + g * HSTRIDE + col) = lo;
                *(float2*)(hb + (g + 8) * HSTRIDE + col) = hi;
                if (tig < 2) {
                    int col1 = 8 + 2 * tig;
                    float2 lo1 = make_float2(__uint_as_float(cvt_tf32(sigm(zc[1][0]))),
                                             __uint_as_float(cvt_tf32(sigm(zc[1][1]))));
                    float2 hi1 = make_float2(__uint_as_float(cvt_tf32(sigm(zc[1][2]))),
                                             __uint_as_float(cvt_tf32(sigm(zc[1][3]))));
                    *(float2*)(hb + g * HSTRIDE + col1) = lo1;
                    *(float2*)(hb + (g + 8) * HSTRIDE + col1) = hi1;
                }
            }
            __syncwarp();

            // ---- Decoder A-fragments from h tile (k = h, pad >=12 with 0) ----
            uint32_t ha[2][4];
            ha[0][0] = __float_as_uint(hb[g * HSTRIDE + tig]);
            ha[0][1] = __float_as_uint(hb[(g + 8) * HSTRIDE + tig]);
            ha[0][2] = __float_as_uint(hb[g * HSTRIDE + tig + 4]);
            ha[0][3] = __float_as_uint(hb[(g + 8) * HSTRIDE + tig + 4]);
            ha[1][0] = __float_as_uint(hb[g * HSTRIDE + tig + 8]);
            ha[1][1] = __float_as_uint(hb[(g + 8) * HSTRIDE + tig + 8]);
            ha[1][2] = 0u;
            ha[1][3] = 0u;

            // ---- Decoder MMAs + error ----
            #pragma unroll
            for (int nt = 0; nt < 2; ++nt) {
                float rc0 = bdv[nt].x, rc1 = bdv[nt].y, rc2 = bdv[nt].x, rc3 = bdv[nt].y;
                #pragma unroll
                for (int kg = 0; kg < 2; ++kg)
                    mma_tf32(rc0, rc1, rc2, rc3,
                             ha[kg][0], ha[kg][1], ha[kg][2], ha[kg][3],
                             wdb[nt][kg][0], wdb[nt][kg][1]);
                int col = 8 * nt + 2 * tig;
                float2 x0 = *(const float2*)(xb + g * XSTRIDE + col);
                float2 x1 = *(const float2*)(xb + (g + 8) * XSTRIDE + col);
                float d0 = sigm(rc0) - x0.x;
                float d1 = sigm(rc1) - x0.y;
                float d2 = sigm(rc2) - x1.x;
                float d3 = sigm(rc3) - x1.y;
                e = fmaf(d0, d0, e); e = fmaf(d1, d1, e);
                e = fmaf(d2, d2, e); e = fmaf(d3, d3, e);
            }
        }

        // Per-cluster warp reduction -> shared partial
        #pragma unroll
        for (int off = 16; off > 0; off >>= 1)
            e += __shfl_xor_sync(0xffffffffu, e, off);
        if (lane == 0) atomicAdd(smf + SP_S + c, e);
    }

    __syncthreads();
    if (tid < C) atomicAdd(&g_sumsq[tid], smf[SP_S + tid]);
    __threadfence();
    __syncthreads();

    // Last-block-done: tiny head in-kernel; reset scratch for next graph replay.
    __shared__ unsigned int s_islast;
    if (tid == 0) s_islast = (atomicAdd(&g_done, 1u) == (unsigned)(NBLOCKS - 1)) ? 1u : 0u;
    __syncthreads();

    if (s_islast) {
        __shared__ float tails_s[C];
        __shared__ float h2_s[HH];
        if (tid < C) {
            float l = sqrtf(g_sumsq[tid] * INV_COUNT);
            if (l == 0.0f) l = 0.01f;
            tails_s[tid] = l;
            out[C + tid] = l;
            g_sumsq[tid] = 0.0f;
        }
        __syncthreads();
        if (tid < HH) {
            float a = hbe[tid];
            #pragma unroll
            for (int cc = 0; cc < C; ++cc) a = fmaf(He[tid * C + cc], tails_s[cc], a);
            h2_s[tid] = 1.0f / (1.0f + expf(-a));
        }
        __syncthreads();
        if (tid < C) {
            float a = hbd[tid];
            #pragma unroll
            for (int j = 0; j < HH; ++j) a = fmaf(Hd[tid * HH + j], h2_s[j], a);
            out[tid] = 1.0f / (1.0f + expf(-a));
        }
        if (tid == 0) g_done = 0u;
    }
}

extern "C" void kernel_launch(void* const* d_in, const int* in_sizes, int n_in,
                              void* d_out, int out_size) {
    const float* x   = (const float*)d_in[0];
    const float* We  = (const float*)d_in[1];
    const float* be  = (const float*)d_in[2];
    const float* Wd  = (const float*)d_in[3];
    const float* bd  = (const float*)d_in[4];
    const float* He  = (const float*)d_in[5];
    const float* hbe = (const float*)d_in[6];
    const float* Hd  = (const float*)d_in[7];
    const float* hbd = (const float*)d_in[8];
    // d_in[9] = cluster_idx: identity arange by construction, elided.
    float* out = (float*)d_out;

    static bool attr_set = false;
    if (!attr_set) {
        cudaFuncSetAttribute(autoenc_mma_kernel,
                             cudaFuncAttributeMaxDynamicSharedMemorySize, SMEM_BYTES);
        attr_set = true;
    }
    autoenc_mma_kernel<<<NBLOCKS, THREADS, SMEM_BYTES>>>(
        x, We, be, Wd, bd, He, hbe, Hd, hbd, out);
}

// round 12
// speedup vs baseline: 1.0054x; 1.0054x over previous
#include <cuda_runtime.h>
#include <math.h>
#include <stdint.h>

#define C 16
#define F 16
#define H 12
#define HH 12
#define BROWS 262144
#define THREADS 256
#define NWARPS 8
#define ROWS_PER_WARP 32
#define ROWS_PER_BLOCK 256
#define NBLOCKS (BROWS / ROWS_PER_BLOCK)   // 1024
#define INV_COUNT (1.0f / 4194304.0f)

// Dynamic smem (float units)
#define XSTRIDE 20                         // bank-conflict-free frag loads, 16B-aligned rows
#define XWARP 1280                         // per-warp: 2 bufs x 32 rows x 20
#define XB0   0                            // 8 warps * 1280 = 10240
#define WE_S  (XB0 + NWARPS * XWARP)       // 10240; [16][12] stride 17 = 3264
#define WD_S  (WE_S + 16 * 12 * 17)        // 13504; [16][16] stride 12 = 3072
#define BE_S  (WD_S + 16 * 16 * 12)        // 16576; [16][16]
#define BD_S  (BE_S + 256)                 // 16832; [16][16]
#define SP_S  (BD_S + 256)                 // 17088
#define SMEM_FLOATS (SP_S + 16)            // 17104
#define SMEM_BYTES (SMEM_FLOATS * 4)       // 68416 B -> 3 CTAs/SM

__device__ float g_sumsq[C];
__device__ unsigned int g_done;

__device__ __forceinline__ float tanh_ap(float x) {
    float y; asm("tanh.approx.f32 %0, %1;" : "=f"(y) : "f"(x)); return y;
}
__device__ __forceinline__ float sigm(float z) {
    return fmaf(0.5f, tanh_ap(0.5f * z), 0.5f);
}
__device__ __forceinline__ uint32_t cvt_tf32(float x) {
    uint32_t u; asm("cvt.rna.tf32.f32 %0, %1;" : "=r"(u) : "f"(x)); return u;
}
__device__ __forceinline__ void mma_tf32(float& c0, float& c1, float& c2, float& c3,
                                         uint32_t a0, uint32_t a1, uint32_t a2, uint32_t a3,
                                         uint32_t b0, uint32_t b1) {
    asm("mma.sync.aligned.m16n8k8.row.col.f32.tf32.tf32.f32 "
        "{%0,%1,%2,%3}, {%4,%5,%6,%7}, {%8,%9}, {%0,%1,%2,%3};"
        : "+f"(c0), "+f"(c1), "+f"(c2), "+f"(c3)
        : "r"(a0), "r"(a1), "r"(a2), "r"(a3), "r"(b0), "r"(b1));
}
__device__ __forceinline__ uint32_t smem_u32(const void* p) {
    return (uint32_t)__cvta_generic_to_shared(p);
}
__device__ __forceinline__ void cp16(uint32_t dst, const void* src) {
    asm volatile("cp.async.ca.shared.global [%0], [%1], 16;" :: "r"(dst), "l"(src));
}

__global__ __launch_bounds__(THREADS, 3) void autoenc_mma_kernel(
    const float* __restrict__ x,
    const float* __restrict__ gWe,  // [C][H][F]
    const float* __restrict__ gbe,  // [C][H]
    const float* __restrict__ gWd,  // [C][F][H]
    const float* __restrict__ gbd,  // [C][F]
    const float* __restrict__ He,   // [HH][C]
    const float* __restrict__ hbe,  // [HH]
    const float* __restrict__ Hd,   // [C][HH]
    const float* __restrict__ hbd,  // [C]
    float* __restrict__ out)        // [0:16) head_out, [16:32) tails
{
    extern __shared__ __align__(16) float smf[];
    const int tid  = threadIdx.x;
    const int warp = tid >> 5;
    const int lane = tid & 31;
    const int g    = lane >> 2;   // groupID (row within m16)
    const int tig  = lane & 3;    // thread-in-group
    const bool odd = (tig & 1);

    // ---- Stage weights (tf32) + biases into smem ----
    for (int i = tid; i < C * H * F; i += THREADS) {
        int c = i / (H * F);
        int r = i - c * (H * F);
        int h = r / F;
        int f = r - h * F;
        smf[WE_S + (c * H + h) * 17 + f] = __uint_as_float(cvt_tf32(gWe[i]));
    }
    for (int i = tid; i < C * F * H; i += THREADS) {
        int c = i / (F * H);
        int r = i - c * (F * H);
        int f = r / H;
        int h = r - f * H;
        smf[WD_S + (c * F + f) * 12 + h] = __uint_as_float(cvt_tf32(gWd[i]));
    }
    for (int i = tid; i < 256; i += THREADS) {
        int c = i >> 4, h = i & 15;
        smf[BE_S + i] = (h < H) ? gbe[c * H + h] : 0.0f;
        smf[BD_S + i] = gbd[i];
    }
    if (tid < C) smf[SP_S + tid] = 0.0f;
    __syncthreads();   // the ONLY pre-loop block barrier

    float* xwarp = smf + XB0 + warp * XWARP;
    const size_t myrow = (size_t)blockIdx.x * ROWS_PER_BLOCK + warp * ROWS_PER_WARP + lane;
    const float* xsrc_base = x + myrow * (C * F);   // one row per lane

    // Per-warp cp.async: lane L copies its own row's 64B for cluster c
    auto issue_x = [&](int c, int buf) {
        const float* src = xsrc_base + c * F;
        uint32_t dst = smem_u32(xwarp + buf * 640 + lane * XSTRIDE);
        cp16(dst,      src);
        cp16(dst + 16, src + 4);
        cp16(dst + 32, src + 8);
        cp16(dst + 48, src + 12);
        asm volatile("cp.async.commit_group;");
    };

    issue_x(0, 0);
    int buf = 0;

    #pragma unroll 1
    for (int c = 0; c < C; ++c) {
        __syncwarp();   // all lanes done reading buf^1 (cluster c-1) before overwrite
        if (c < C - 1) issue_x(c + 1, buf ^ 1);
        if (c < C - 1) asm volatile("cp.async.wait_group 1;");
        else           asm volatile("cp.async.wait_group 0;");
        __syncwarp();   // lane i sees lane j's cp.async results for cluster c

        const float* xb_base = xwarp + buf * 640;

        // ---- Weight fragments (per cluster, shared across subtiles) ----
        uint32_t web[2][2][2];
        #pragma unroll
        for (int nt = 0; nt < 2; ++nt) {
            int h = g + 8 * nt;
            bool hv = (h < H);
            const float* wr = smf + WE_S + (c * H + (hv ? h : 0)) * 17;
            #pragma unroll
            for (int kg = 0; kg < 2; ++kg) {
                web[nt][kg][0] = hv ? __float_as_uint(wr[tig + 8 * kg])     : 0u;
                web[nt][kg][1] = hv ? __float_as_uint(wr[tig + 4 + 8 * kg]) : 0u;
            }
        }
        uint32_t wdb[2][2][2];
        #pragma unroll
        for (int nt = 0; nt < 2; ++nt) {
            int f = g + 8 * nt;
            const float* wr = smf + WD_S + (c * F + f) * 12;
            wdb[nt][0][0] = __float_as_uint(wr[tig]);
            wdb[nt][0][1] = __float_as_uint(wr[tig + 4]);
            wdb[nt][1][0] = __float_as_uint(wr[tig + 8]);
            wdb[nt][1][1] = 0u;
        }
        float2 bev[2], bdv[2];
        #pragma unroll
        for (int nt = 0; nt < 2; ++nt) {
            bev[nt] = *(const float2*)(smf + BE_S + c * 16 + 8 * nt + 2 * tig);
            bdv[nt] = *(const float2*)(smf + BD_S + c * 16 + 8 * nt + 2 * tig);
        }

        float e = 0.0f;

        #pragma unroll
        for (int s = 0; s < 2; ++s) {
            const float* xb = xb_base + s * 16 * XSTRIDE;

            // ---- x A-fragments (k = f) ----
            uint32_t xa[2][4];
            #pragma unroll
            for (int kg = 0; kg < 2; ++kg) {
                xa[kg][0] = cvt_tf32(xb[g * XSTRIDE + tig + 8 * kg]);
                xa[kg][1] = cvt_tf32(xb[(g + 8) * XSTRIDE + tig + 8 * kg]);
                xa[kg][2] = cvt_tf32(xb[g * XSTRIDE + tig + 4 + 8 * kg]);
                xa[kg][3] = cvt_tf32(xb[(g + 8) * XSTRIDE + tig + 4 + 8 * kg]);
            }

            // ---- Encoder MMAs ----
            float zc[2][4];
            #pragma unroll
            for (int nt = 0; nt < 2; ++nt) {
                zc[nt][0] = bev[nt].x; zc[nt][1] = bev[nt].y;
                zc[nt][2] = bev[nt].x; zc[nt][3] = bev[nt].y;
                #pragma unroll
                for (int kg = 0; kg < 2; ++kg)
                    mma_tf32(zc[nt][0], zc[nt][1], zc[nt][2], zc[nt][3],
                             xa[kg][0], xa[kg][1], xa[kg][2], xa[kg][3],
                             web[nt][kg][0], web[nt][kg][1]);
            }

            // ---- sigmoid (owner lanes) + tf32 bits ----
            uint32_t p[2][4];
            #pragma unroll
            for (int nt = 0; nt < 2; ++nt)
                #pragma unroll
                for (int i = 0; i < 4; ++i)
                    p[nt][i] = cvt_tf32(sigm(zc[nt][i]));

            // ---- C-layout -> A-layout via warp shuffles (no smem) ----
            // H[r][col] owner: lane 4*(r%8) + (col_in_tile>>1), parity col&1;
            // rows r and r+8 are regs {0,1} vs {2,3} of the SAME lane.
            int srcA = 4 * g + (tig >> 1);      // nt0 cols tig  / nt1 cols tig+8
            int srcB = srcA + 2;                // nt0 cols tig+4
            uint32_t v0 = __shfl_sync(~0u, p[0][0], srcA);
            uint32_t v1 = __shfl_sync(~0u, p[0][1], srcA);
            uint32_t v2 = __shfl_sync(~0u, p[0][2], srcA);
            uint32_t v3 = __shfl_sync(~0u, p[0][3], srcA);
            uint32_t w0 = __shfl_sync(~0u, p[0][0], srcB);
            uint32_t w1 = __shfl_sync(~0u, p[0][1], srcB);
            uint32_t w2 = __shfl_sync(~0u, p[0][2], srcB);
            uint32_t w3 = __shfl_sync(~0u, p[0][3], srcB);
            uint32_t u0 = __shfl_sync(~0u, p[1][0], srcA);
            uint32_t u1 = __shfl_sync(~0u, p[1][1], srcA);
            uint32_t u2 = __shfl_sync(~0u, p[1][2], srcA);
            uint32_t u3 = __shfl_sync(~0u, p[1][3], srcA);

            uint32_t ha[2][4];
            ha[0][0] = odd ? v1 : v0;   // H[g][tig]
            ha[0][1] = odd ? v3 : v2;   // H[g+8][tig]
            ha[0][2] = odd ? w1 : w0;   // H[g][tig+4]
            ha[0][3] = odd ? w3 : w2;   // H[g+8][tig+4]
            ha[1][0] = odd ? u1 : u0;   // H[g][tig+8]
            ha[1][1] = odd ? u3 : u2;   // H[g+8][tig+8]
            ha[1][2] = 0u;              // h = tig+12 pad
            ha[1][3] = 0u;

            // ---- Decoder MMAs + error ----
            #pragma unroll
            for (int nt = 0; nt < 2; ++nt) {
                float rc0 = bdv[nt].x, rc1 = bdv[nt].y, rc2 = bdv[nt].x, rc3 = bdv[nt].y;
                #pragma unroll
                for (int kg = 0; kg < 2; ++kg)
                    mma_tf32(rc0, rc1, rc2, rc3,
                             ha[kg][0], ha[kg][1], ha[kg][2], ha[kg][3],
                             wdb[nt][kg][0], wdb[nt][kg][1]);
                int col = 8 * nt + 2 * tig;
                float2 x0 = *(const float2*)(xb + g * XSTRIDE + col);
                float2 x1 = *(const float2*)(xb + (g + 8) * XSTRIDE + col);
                float d0 = sigm(rc0) - x0.x;
                float d1 = sigm(rc1) - x0.y;
                float d2 = sigm(rc2) - x1.x;
                float d3 = sigm(rc3) - x1.y;
                e = fmaf(d0, d0, e); e = fmaf(d1, d1, e);
                e = fmaf(d2, d2, e); e = fmaf(d3, d3, e);
            }
        }

        // Per-cluster warp reduction -> shared partial
        #pragma unroll
        for (int off = 16; off > 0; off >>= 1)
            e += __shfl_xor_sync(0xffffffffu, e, off);
        if (lane == 0) atomicAdd(smf + SP_S + c, e);

        buf ^= 1;
    }

    __syncthreads();
    if (tid < C) atomicAdd(&g_sumsq[tid], smf[SP_S + tid]);
    __threadfence();
    __syncthreads();

    // Last-block-done: tiny head in-kernel; reset scratch for next graph replay.
    __shared__ unsigned int s_islast;
    if (tid == 0) s_islast = (atomicAdd(&g_done, 1u) == (unsigned)(NBLOCKS - 1)) ? 1u : 0u;
    __syncthreads();

    if (s_islast) {
        __shared__ float tails_s[C];
        __shared__ float h2_s[HH];
        if (tid < C) {
            float l = sqrtf(g_sumsq[tid] * INV_COUNT);
            if (l == 0.0f) l = 0.01f;
            tails_s[tid] = l;
            out[C + tid] = l;
            g_sumsq[tid] = 0.0f;
        }
        __syncthreads();
        if (tid < HH) {
            float a = hbe[tid];
            #pragma unroll
            for (int cc = 0; cc < C; ++cc) a = fmaf(He[tid * C + cc], tails_s[cc], a);
            h2_s[tid] = 1.0f / (1.0f + expf(-a));
        }
        __syncthreads();
        if (tid < C) {
            float a = hbd[tid];
            #pragma unroll
            for (int j = 0; j < HH; ++j) a = fmaf(Hd[tid * HH + j], h2_s[j], a);
            out[tid] = 1.0f / (1.0f + expf(-a));
        }
        if (tid == 0) g_done = 0u;
    }
}

extern "C" void kernel_launch(void* const* d_in, const int* in_sizes, int n_in,
                              void* d_out, int out_size) {
    const float* x   = (const float*)d_in[0];
    const float* We  = (const float*)d_in[1];
    const float* be  = (const float*)d_in[2];
    const float* Wd  = (const float*)d_in[3];
    const float* bd  = (const float*)d_in[4];
    const float* He  = (const float*)d_in[5];
    const float* hbe = (const float*)d_in[6];
    const float* Hd  = (const float*)d_in[7];
    const float* hbd = (const float*)d_in[8];
    // d_in[9] = cluster_idx: identity arange by construction, elided.
    float* out = (float*)d_out;

    static bool attr_set = false;
    if (!attr_set) {
        cudaFuncSetAttribute(autoenc_mma_kernel,
                             cudaFuncAttributeMaxDynamicSharedMemorySize, SMEM_BYTES);
        attr_set = true;
    }
    autoenc_mma_kernel<<<NBLOCKS, THREADS, SMEM_BYTES>>>(
        x, We, be, Wd, bd, He, hbe, Hd, hbd, out);
}

// round 13
// speedup vs baseline: 1.2517x; 1.2451x over previous
#include <cuda_runtime.h>
#include <math.h>

#define C 16
#define F 16
#define H 12
#define HH 12
#define BROWS 262144
#define THREADS 128
#define ROWS_PER_THREAD 2
#define NBLOCKS (BROWS / (THREADS * ROWS_PER_THREAD))  // 1024
#define INV_COUNT (1.0f / 4194304.0f)

// Contiguous constant weight bank (natural layouts, raw values)
#define WE0 0
#define WD0 3072
#define BE0 6144
#define BD0 6336
#define WTOT 6592

typedef unsigned long long u64;

__constant__ float cw[WTOT];
__device__ float g_scratch[WTOT];
__device__ float g_sumsq[C];
__device__ unsigned int g_done;

__device__ __forceinline__ u64 pack2(float lo, float hi) {
    u64 r; asm("mov.b64 %0, {%1, %2};" : "=l"(r) : "f"(lo), "f"(hi)); return r;
}
__device__ __forceinline__ void unpack2(u64 v, float& lo, float& hi) {
    asm("mov.b64 {%0, %1}, %2;" : "=f"(lo), "=f"(hi) : "l"(v));
}
__device__ __forceinline__ u64 ffma2(u64 a, u64 b, u64 c) {
    u64 d; asm("fma.rn.f32x2 %0, %1, %2, %3;" : "=l"(d) : "l"(a), "l"(b), "l"(c)); return d;
}
__device__ __forceinline__ float tanh_ap(float x) {
    float y; asm("tanh.approx.f32 %0, %1;" : "=f"(y) : "f"(x)); return y;
}
__device__ __forceinline__ u64 tanh2(u64 v) {
    float lo, hi; unpack2(v, lo, hi);
    return pack2(tanh_ap(lo), tanh_ap(hi));
}
__device__ __forceinline__ float hadd(u64 v) {
    float lo, hi; unpack2(v, lo, hi); return lo + hi;
}

// Pack all weights into one contiguous scratch bank (single D2D memcpy after).
__global__ void prep_kernel(const float* __restrict__ We,
                            const float* __restrict__ be,
                            const float* __restrict__ Wd,
                            const float* __restrict__ bd)
{
    int i = blockIdx.x * blockDim.x + threadIdx.x;
    if (i < C * H * F) {
        g_scratch[WE0 + i] = We[i];
        g_scratch[WD0 + i] = Wd[i];
    }
    if (i < C * H) g_scratch[BE0 + i] = be[i];
    if (i < C * F) g_scratch[BD0 + i] = bd[i];
}

__global__ __launch_bounds__(THREADS, 4) void autoenc_fused_kernel(
    const float* __restrict__ x,
    const float* __restrict__ He,   // [HH][C]
    const float* __restrict__ hbe,  // [HH]
    const float* __restrict__ Hd,   // [C][HH]
    const float* __restrict__ hbd,  // [C]
    float* __restrict__ out)        // [0:16) head_out, [16:32) tails
{
    __shared__ float spart[C];
    const int tid = threadIdx.x;
    const int lane = tid & 31;
    if (tid < C) spart[tid] = 0.0f;
    __syncthreads();

    const size_t base = (size_t)blockIdx.x * (THREADS * ROWS_PER_THREAD) + tid;
    const float4* __restrict__ xr0 = (const float4*)(x + (base          ) * (C * F));
    const float4* __restrict__ xr1 = (const float4*)(x + (base + THREADS) * (C * F));

    const u64 half2 = pack2(0.5f, 0.5f);
    const u64 quart2 = pack2(0.25f, 0.25f);
    const u64 negone2 = pack2(-1.0f, -1.0f);

    // ---- Prefetch cluster 0's x into registers ----
    float4 pf0[4], pf1[4];
    #pragma unroll
    for (int k = 0; k < 4; ++k) { pf0[k] = xr0[k]; pf1[k] = xr1[k]; }

    #pragma unroll 1
    for (int c = 0; c < C; ++c) {
        // Consume prefetch into f-pair registers
        u64 xp0[8], xp1[8];
        #pragma unroll
        for (int k = 0; k < 4; ++k) {
            xp0[2 * k] = pack2(pf0[k].x, pf0[k].y);
            xp0[2 * k + 1] = pack2(pf0[k].z, pf0[k].w);
            xp1[2 * k] = pack2(pf1[k].x, pf1[k].y);
            xp1[2 * k + 1] = pack2(pf1[k].z, pf1[k].w);
        }
        // Issue next cluster's loads NOW — they complete under this cluster's compute
        if (c < C - 1) {
            #pragma unroll
            for (int k = 0; k < 4; ++k) {
                pf0[k] = xr0[(c + 1) * 4 + k];
                pf1[k] = xr1[(c + 1) * 4 + k];
            }
        }

        // ---- Encoder: per h-pair, two independent 8-FFMA2 dot chains per row ----
        u64 hp0[6], hp1[6];
        #pragma unroll
        for (int j = 0; j < 6; ++j) {
            const ulonglong2* wI = (const ulonglong2*)(cw + WE0 + (c * H + 2 * j) * F);
            const ulonglong2* wJ = (const ulonglong2*)(cw + WE0 + (c * H + 2 * j + 1) * F);
            ulonglong2 ia = wI[0], ib = wI[1], ic = wI[2], id = wI[3];
            ulonglong2 ja = wJ[0], jb = wJ[1], jc = wJ[2], jd = wJ[3];
            u64 a00 = 0ull, a01 = 0ull, a10 = 0ull, a11 = 0ull;
            a00 = ffma2(xp0[0], ia.x, a00); a01 = ffma2(xp0[0], ja.x, a01);
            a10 = ffma2(xp1[0], ia.x, a10); a11 = ffma2(xp1[0], ja.x, a11);
            a00 = ffma2(xp0[1], ia.y, a00); a01 = ffma2(xp0[1], ja.y, a01);
            a10 = ffma2(xp1[1], ia.y, a10); a11 = ffma2(xp1[1], ja.y, a11);
            a00 = ffma2(xp0[2], ib.x, a00); a01 = ffma2(xp0[2], jb.x, a01);
            a10 = ffma2(xp1[2], ib.x, a10); a11 = ffma2(xp1[2], jb.x, a11);
            a00 = ffma2(xp0[3], ib.y, a00); a01 = ffma2(xp0[3], jb.y, a01);
            a10 = ffma2(xp1[3], ib.y, a10); a11 = ffma2(xp1[3], jb.y, a11);
            a00 = ffma2(xp0[4], ic.x, a00); a01 = ffma2(xp0[4], jc.x, a01);
            a10 = ffma2(xp1[4], ic.x, a10); a11 = ffma2(xp1[4], jc.x, a11);
            a00 = ffma2(xp0[5], ic.y, a00); a01 = ffma2(xp0[5], jc.y, a01);
            a10 = ffma2(xp1[5], ic.y, a10); a11 = ffma2(xp1[5], jc.y, a11);
            a00 = ffma2(xp0[6], id.x, a00); a01 = ffma2(xp0[6], jd.x, a01);
            a10 = ffma2(xp1[6], id.x, a10); a11 = ffma2(xp1[6], jd.x, a11);
            a00 = ffma2(xp0[7], id.y, a00); a01 = ffma2(xp0[7], jd.y, a01);
            a10 = ffma2(xp1[7], id.y, a10); a11 = ffma2(xp1[7], jd.y, a11);

            float bh0 = 0.5f * cw[BE0 + c * H + 2 * j];
            float bh1 = 0.5f * cw[BE0 + c * H + 2 * j + 1];
            float e00 = tanh_ap(fmaf(0.5f, hadd(a00), bh0));
            float e01 = tanh_ap(fmaf(0.5f, hadd(a01), bh1));
            float e10 = tanh_ap(fmaf(0.5f, hadd(a10), bh0));
            float e11 = tanh_ap(fmaf(0.5f, hadd(a11), bh1));
            // hp = 0.5*sigmoid = 0.25*tanh + 0.25 (folds decoder's 0.5 scale)
            hp0[j] = ffma2(pack2(e00, e01), quart2, quart2);
            hp1[j] = ffma2(pack2(e10, e11), quart2, quart2);
        }

        // ---- Decoder: per f-pair, dot over h in pairs; Wd rows h-contig ----
        u64 ev0 = 0ull, ev1 = 0ull;
        const u64* bdU = (const u64*)(cw + BD0 + c * F);
        #pragma unroll
        for (int fp = 0; fp < 8; ++fp) {
            const ulonglong2* wA = (const ulonglong2*)(cw + WD0 + (c * F + 2 * fp) * H);
            const ulonglong2* wB = (const ulonglong2*)(cw + WD0 + (c * F + 2 * fp + 1) * H);
            ulonglong2 a01v = wA[0], a23 = wA[1], a45 = wA[2];
            ulonglong2 b01 = wB[0], b23 = wB[1], b45 = wB[2];

            u64 sa0 = 0ull, sb0 = 0ull, sa1 = 0ull, sb1 = 0ull;
            sa0 = ffma2(hp0[0], a01v.x, sa0); sb0 = ffma2(hp0[0], b01.x, sb0);
            sa1 = ffma2(hp1[0], a01v.x, sa1); sb1 = ffma2(hp1[0], b01.x, sb1);
            sa0 = ffma2(hp0[1], a01v.y, sa0); sb0 = ffma2(hp0[1], b01.y, sb0);
            sa1 = ffma2(hp1[1], a01v.y, sa1); sb1 = ffma2(hp1[1], b01.y, sb1);
            sa0 = ffma2(hp0[2], a23.x, sa0); sb0 = ffma2(hp0[2], b23.x, sb0);
            sa1 = ffma2(hp1[2], a23.x, sa1); sb1 = ffma2(hp1[2], b23.x, sb1);
            sa0 = ffma2(hp0[3], a23.y, sa0); sb0 = ffma2(hp0[3], b23.y, sb0);
            sa1 = ffma2(hp1[3], a23.y, sa1); sb1 = ffma2(hp1[3], b23.y, sb1);
            sa0 = ffma2(hp0[4], a45.x, sa0); sb0 = ffma2(hp0[4], b45.x, sb0);
            sa1 = ffma2(hp1[4], a45.x, sa1); sb1 = ffma2(hp1[4], b45.x, sb1);
            sa0 = ffma2(hp0[5], a45.y, sa0); sb0 = ffma2(hp0[5], b45.y, sb0);
            sa1 = ffma2(hp1[5], a45.y, sa1); sb1 = ffma2(hp1[5], b45.y, sb1);

            u64 bdp = bdU[fp];
            u64 t0 = ffma2(bdp, half2, pack2(hadd(sa0), hadd(sb0)));
            u64 t1 = ffma2(bdp, half2, pack2(hadd(sa1), hadd(sb1)));
            u64 rec0 = ffma2(tanh2(t0), half2, half2);
            u64 rec1 = ffma2(tanh2(t1), half2, half2);
            u64 d0 = ffma2(xp0[fp], negone2, rec0);
            u64 d1 = ffma2(xp1[fp], negone2, rec1);
            ev0 = ffma2(d0, d0, ev0);
            ev1 = ffma2(d1, d1, ev1);
        }

        float e = hadd(ev0) + hadd(ev1);
        #pragma unroll
        for (int off = 16; off > 0; off >>= 1)
            e += __shfl_xor_sync(0xffffffffu, e, off);
        if (lane == 0) atomicAdd(&spart[c], e);
    }

    __syncthreads();
    if (tid < C) atomicAdd(&g_sumsq[tid], spart[tid]);
    __threadfence();
    __syncthreads();

    // Last-block-done: tiny head in-kernel; reset scratch for next graph replay.
    __shared__ unsigned int s_islast;
    if (tid == 0) s_islast = (atomicAdd(&g_done, 1u) == (unsigned)(NBLOCKS - 1)) ? 1u : 0u;
    __syncthreads();

    if (s_islast) {
        __shared__ float tails_s[C];
        __shared__ float h2_s[HH];
        if (tid < C) {
            float l = sqrtf(g_sumsq[tid] * INV_COUNT);
            if (l == 0.0f) l = 0.01f;
            tails_s[tid] = l;
            out[C + tid] = l;
            g_sumsq[tid] = 0.0f;
        }
        __syncthreads();
        if (tid < HH) {
            float a = hbe[tid];
            #pragma unroll
            for (int cc = 0; cc < C; ++cc) a = fmaf(He[tid * C + cc], tails_s[cc], a);
            h2_s[tid] = 1.0f / (1.0f + expf(-a));
        }
        __syncthreads();
        if (tid < C) {
            float a = hbd[tid];
            #pragma unroll
            for (int j = 0; j < HH; ++j) a = fmaf(Hd[tid * HH + j], h2_s[j], a);
            out[tid] = 1.0f / (1.0f + expf(-a));
        }
        if (tid == 0) g_done = 0u;
    }
}

extern "C" void kernel_launch(void* const* d_in, const int* in_sizes, int n_in,
                              void* d_out, int out_size) {
    const float* x   = (const float*)d_in[0];
    const float* We  = (const float*)d_in[1];
    const float* be  = (const float*)d_in[2];
    const float* Wd  = (const float*)d_in[3];
    const float* bd  = (const float*)d_in[4];
    const float* He  = (const float*)d_in[5];
    const float* hbe = (const float*)d_in[6];
    const float* Hd  = (const float*)d_in[7];
    const float* hbd = (const float*)d_in[8];
    // d_in[9] = cluster_idx: identity arange by construction, elided.
    float* out = (float*)d_out;

    static void* scratch_ptr = nullptr;
    if (!scratch_ptr) cudaGetSymbolAddress(&scratch_ptr, g_scratch);

    prep_kernel<<<(C * H * F + 255) / 256, 256>>>(We, be, Wd, bd);
    cudaMemcpyToSymbolAsync(cw, scratch_ptr, WTOT * sizeof(float), 0,
                            cudaMemcpyDeviceToDevice, 0);
    autoenc_fused_kernel<<<NBLOCKS, THREADS>>>(x, He, hbe, Hd, hbd, out);
}